// round 8
// baseline (speedup 1.0000x reference)
#include <cuda_runtime.h>

// MultiDense: out[i,j,l] = sum_k x[i,j,k] * params[inds[i], l, k] + params[inds[i], l, 128]
// I=8192, J=32, IN_F=128, OUT_F=128, params row = 128*129 floats.
//
// One CTA per i. Stage params row (fp32) + j-paired x (float2) in smem.
// Thread t owns output column l=t; 16 j-pair accumulators as packed f32x2,
// updated with Blackwell fma.rn.f32x2 (2 fp32 FMAs per issue).
//
// NOTE: inds expected int32 (JAX default config downcasts the reference's
// int64). Index is masked to [0, 4096) so a dtype surprise can never IMA.

#define I_DIM 8192
#define J_DIM 32
#define IN_F  128
#define OUT_F 128
#define PROW  129                         // IN_F + 1 (weights + bias)
#define NODE_MASK 4095                    // NUM_NODES - 1 (power of two)
#define X_FLOATS (J_DIM * IN_F)           // 4096
#define W_FLOATS (OUT_F * PROW)           // 16512
#define XP_PAIRS (X_FLOATS / 2)           // 2048 float2 elements
// smem: Ws fp32 [66048 B] + Xp float2 [16384 B]
#define SMEM_BYTES (W_FLOATS * 4 + XP_PAIRS * 8)   // 82432

__device__ __forceinline__ unsigned long long ffma2(unsigned long long a,
                                                    unsigned long long b,
                                                    unsigned long long c)
{
    unsigned long long d;
    asm("fma.rn.f32x2 %0, %1, %2, %3;" : "=l"(d) : "l"(a), "l"(b), "l"(c));
    return d;
}

__device__ __forceinline__ unsigned long long pack2(float lo, float hi)
{
    unsigned long long d;
    asm("mov.b64 %0, {%1, %2};" : "=l"(d) : "f"(lo), "f"(hi));
    return d;
}

__global__ __launch_bounds__(128, 2)
void multidense_kernel(const float* __restrict__ x_in,
                       const int* __restrict__ inds,
                       const float* __restrict__ params,
                       float* __restrict__ out)
{
    extern __shared__ float smem[];
    float*  Ws = smem;                                       // [OUT_F][PROW]
    float2* Xp = reinterpret_cast<float2*>(smem + W_FLOATS); // [16 jpairs][IN_F]

    const int i = blockIdx.x;
    const int t = threadIdx.x;            // 0..127
    const int node = inds[i] & NODE_MASK; // int32 index; mask guarantees in-bounds

    // ---- stage params row (16512 floats = 4128 float4), coalesced ----
    {
        const float4* pg = reinterpret_cast<const float4*>(params + (size_t)node * W_FLOATS);
        float4* ws4 = reinterpret_cast<float4*>(Ws);
        #pragma unroll
        for (int r = 0; r < 32; r++)
            ws4[t + r * 128] = pg[t + r * 128];
        if (t < 32)
            ws4[4096 + t] = pg[4096 + t];   // tail 32 float4
    }

    // ---- stage x as j-paired float2: Xp[p*IN_F + k] = (x[2p][k], x[2p+1][k]) ----
    {
        const float* xg = x_in + (size_t)i * X_FLOATS;
        #pragma unroll
        for (int r = 0; r < XP_PAIRS / 128; r++) {        // 16 iters
            int idx = t + r * 128;                        // 0..2047
            int p = idx >> 7;                             // j-pair
            int k = idx & 127;
            float a = xg[(2 * p) * IN_F + k];
            float b = xg[(2 * p + 1) * IN_F + k];
            Xp[idx] = make_float2(a, b);
        }
    }

    __syncthreads();

    // ---- compute: thread t owns output column l = t; 16 f32x2 accumulators ----
    const int l = t;
    unsigned long long acc[J_DIM / 2];
    #pragma unroll
    for (int p = 0; p < J_DIM / 2; p++) acc[p] = 0ull;

    // W row: stride 129 floats -> bank (l + k) % 32, conflict-free scalar LDS.
    const float* wrow = Ws + l * PROW;
    // Xp viewed as 16B chunks: each ulonglong2 = {pair(k), pair(k+1)}.
    const ulonglong2* xpv = reinterpret_cast<const ulonglong2*>(Xp);

    #pragma unroll 2
    for (int kk = 0; kk < IN_F / 4; kk++) {
        const float w0 = wrow[kk * 4 + 0];
        const float w1 = wrow[kk * 4 + 1];
        const float w2 = wrow[kk * 4 + 2];
        const float w3 = wrow[kk * 4 + 3];
        const unsigned long long wp0 = pack2(w0, w0);
        const unsigned long long wp1 = pack2(w1, w1);
        const unsigned long long wp2 = pack2(w2, w2);
        const unsigned long long wp3 = pack2(w3, w3);

        #pragma unroll
        for (int p = 0; p < J_DIM / 2; p++) {
            const ulonglong2 v01 = xpv[p * 64 + 2 * kk];      // pairs for k0,k1 (broadcast)
            const ulonglong2 v23 = xpv[p * 64 + 2 * kk + 1];  // pairs for k2,k3
            unsigned long long a = acc[p];
            a = ffma2(v01.x, wp0, a);
            a = ffma2(v01.y, wp1, a);
            a = ffma2(v23.x, wp2, a);
            a = ffma2(v23.y, wp3, a);
            acc[p] = a;
        }
    }

    const float bias = wrow[IN_F];
    float* og = out + (size_t)i * (J_DIM * OUT_F) + l;
    #pragma unroll
    for (int p = 0; p < J_DIM / 2; p++) {
        float r0, r1;
        asm("mov.b64 {%0, %1}, %2;" : "=f"(r0), "=f"(r1) : "l"(acc[p]));
        og[(2 * p)     * OUT_F] = r0 + bias;   // lane-stride 1, coalesced
        og[(2 * p + 1) * OUT_F] = r1 + bias;
    }
}

extern "C" void kernel_launch(void* const* d_in, const int* in_sizes, int n_in,
                              void* d_out, int out_size)
{
    const float* x_in   = (const float*)d_in[0];
    const int*   inds   = (const int*)d_in[1];
    const float* params = (const float*)d_in[2];
    float*       out    = (float*)d_out;

    // Host-side immediate call (graph-capture safe); set once.
    static bool attr_set = false;
    if (!attr_set) {
        cudaFuncSetAttribute(multidense_kernel,
                             cudaFuncAttributeMaxDynamicSharedMemorySize, SMEM_BYTES);
        attr_set = true;
    }

    multidense_kernel<<<I_DIM, 128, SMEM_BYTES>>>(x_in, inds, params, out);
}